// round 16
// baseline (speedup 1.0000x reference)
#include <cuda_runtime.h>
#include <cstdint>

// ---------------------------------------------------------------------------
// SparseResUQueryNet R16 = R15 (best: 227.4us) + deeper ILP scaling:
//   (1) k_bb_pool: 8 voxels per warp (VPW 4 -> 8), front-loading 16
//       independent loads (8x g_mr uint2 + 8x hfeat).
//   (2) k_query: 4 hit points per warp (PPW 2 -> 4), front-loading 4
//       independent uint4 worklist entries + per-lane metadata.
//
// Keys: 28-bit ((t*256+x)*256+y)*256+z, t<16, coords in [1,250] (no byte
// carry under +-1). Pool keys 25-bit (b<2). Linear bitmaps bm1/bm2; pooled
// row = rank2(pk) = prefix-popcount over bm2 (single-pass decoupled-lookback
// scan). H1 hash key->feature (EMPTY=0; packed keys never 0 since z>=1),
// probed only for non-self neighbor hits (~45k). maskQ writes the 4-float
// output header for all points, zero-fills no-hit feature rows (~58%), and
// compacts hits into a fat worklist uint4{p, mask, key, 0}. Contested pool
// cells (~1%): detected at insert, rows pre-zeroed in maskH, pooled via
// order-preserving-uint atomicMax, decoded on read. Tail cleanup restores
// the all-zeros scratch invariant for graph replay.
// Launches (7): insert, scan, maskH, bb_pool(profiled), maskQ, query, cleanup.
// ---------------------------------------------------------------------------

#define FULL_MASK 0xFFFFFFFFu
#define H1_LOG 21
#define H1_SIZE (1u << H1_LOG)
#define H1_MASK (H1_SIZE - 1u)
#define BM1_WORDS (1u << 23)
#define BM2_WORDS (1u << 20)
#define CHUNK2 4096
#define NBLK2 (BM2_WORDS / CHUNK2)   // 256
#define NMAX  (1u << 20)
#define AGG_READY 0x40000000u
#define PFX_READY 0x80000000u

__device__ unsigned g_h1_keys[H1_SIZE];               // 8 MB (EMPTY = 0)
__device__ float    g_h1_feat[H1_SIZE];               // 8 MB
__device__ unsigned g_bm1[BM1_WORDS + 2];             // 32 MB (+pad)
__device__ unsigned g_bm2[BM2_WORDS + 2];             // 4 MB  (+pad)
__device__ unsigned g_cont[BM2_WORDS];                // 4 MB contested bits
__device__ unsigned g_pref2[BM2_WORDS];               // 4 MB word prefix
__device__ unsigned g_bstate[NBLK2];                  // lookback states
__device__ int      g_slotOf[NMAX];                   // 4 MB voxel -> H1 slot
__device__ uint2    g_mr[NMAX];                       // 8 MB (mask, row|cont)
__device__ float    g_pooled[(size_t)NMAX * 32];      // 128 MB
__device__ uint4    g_wl[NMAX * 2];                   // 32 MB {p, mask, key, 0}
__device__ int      g_wl_cnt;

// delta[d] = (dx<<16)+(dy<<8)+dz for d = (dx+1)*9+(dy+1)*3+(dz+1)
__constant__ unsigned c_delta[27] = {
    0xFFFEFEFFu, 0xFFFEFF00u, 0xFFFEFF01u,
    0xFFFEFFFFu, 0xFFFF0000u, 0xFFFF0001u,
    0xFFFF00FFu, 0xFFFF0100u, 0xFFFF0101u,
    0xFFFFFEFFu, 0xFFFFFF00u, 0xFFFFFF01u,
    0xFFFFFFFFu, 0x00000000u, 0x00000001u,
    0x000000FFu, 0x00000100u, 0x00000101u,
    0x0000FEFFu, 0x0000FF00u, 0x0000FF01u,
    0x0000FFFFu, 0x00010000u, 0x00010001u,
    0x000100FFu, 0x00010100u, 0x00010101u
};

__device__ __forceinline__ unsigned hash1(unsigned k) {
    return (k * 2654435761u) >> (32 - H1_LOG);
}
__device__ __forceinline__ unsigned encf(float f) {
    unsigned b = __float_as_uint(f);
    return b ^ (unsigned)(((int)b >> 31) | 0x80000000);
}
__device__ __forceinline__ float decf(unsigned u) {
    unsigned x = ((int)u < 0) ? (u ^ 0x80000000u) : ~u;
    return __uint_as_float(x);
}
// 3-bit window; 2nd word only when it spills past bit 31 (6.25%).
__device__ __forceinline__ unsigned tri_at(const unsigned* bm, unsigned bitpos) {
    unsigned idx = bitpos >> 5, sh = bitpos & 31;
    unsigned tri = (bm[idx] >> sh) & 7u;
    if (sh > 29u) tri |= (bm[idx + 1] << (32u - sh)) & 7u;
    return tri;
}
__device__ __forceinline__ unsigned mask27(const unsigned* bm, unsigned key) {
    unsigned mask = 0;
#pragma unroll
    for (int g = 0; g < 9; g++)
        mask |= tri_at(bm, key + c_delta[g * 3]) << (g * 3);
    return mask;
}
__device__ __forceinline__ unsigned rank2_of(unsigned pk) {
    unsigned w = pk >> 5, b = pk & 31;
    return g_pref2[w] + __popc(g_bm2[w] & ((1u << b) - 1u));
}
__device__ __forceinline__ int nth_bit(unsigned mask, int lane) {
    unsigned mm = mask;
    for (int t = 0; t < lane; t++) mm &= mm - 1;
    return __ffs(mm) - 1;
}
__device__ __forceinline__ int block_scan_excl(int v, int tid) {
    __shared__ int sh[256];
    sh[tid] = v;
    __syncthreads();
    for (int off = 1; off < 256; off <<= 1) {
        int add = (tid >= off) ? sh[tid - off] : 0;
        __syncthreads();
        sh[tid] += add;
        __syncthreads();
    }
    int incl = sh[tid];
    __syncthreads();
    return incl - v;
}

// K1: set bits, insert (key,feat) into H1 (record slot), detect contested ----
__global__ void k_insert(const float* __restrict__ hfeat,
                         const int4* __restrict__ hcoord,
                         const int* __restrict__ hbatch, int n) {
    int i = blockIdx.x * blockDim.x + threadIdx.x;
    if (i >= n) return;
    int4 c = hcoord[i];  // t, x, y, z
    unsigned key = ((unsigned)c.x << 24) | ((unsigned)c.y << 16) |
                   ((unsigned)c.z << 8) | (unsigned)c.w;  // never 0 (x,y,z>=1)
    atomicOr(&g_bm1[key >> 5], 1u << (key & 31));
    unsigned s = hash1(key);
    while (true) {  // history keys unique (np.unique upstream)
        unsigned old = atomicCAS(&g_h1_keys[s], 0u, key);
        if (old == 0u) { g_h1_feat[s] = hfeat[i]; g_slotOf[i] = (int)s; break; }
        s = (s + 1) & H1_MASK;
    }
    unsigned pk = ((unsigned)hbatch[i] << 24) | (key & 0x00FFFFFFu);
    unsigned bit = 1u << (pk & 31);
    unsigned prev = atomicOr(&g_bm2[pk >> 5], bit);
    if (prev & bit) atomicOr(&g_cont[pk >> 5], bit);
}

// K2: single-pass bm2 prefix scan (decoupled lookback) ------------------------
__global__ void k_scan() {
    int blk = blockIdx.x, tid = threadIdx.x;
    size_t w0 = (size_t)blk * CHUNK2 + (size_t)tid * 16;
    unsigned wv[16];
    int s = 0;
#pragma unroll
    for (int j = 0; j < 16; j++) { wv[j] = g_bm2[w0 + j]; s += __popc(wv[j]); }
    int ex = block_scan_excl(s, tid);
    __shared__ int sh_tot;
    __shared__ int sh_base;
    if (tid == 255) sh_tot = ex + s;
    __syncthreads();
    if (tid == 0) {
        int btot = sh_tot;
        atomicExch(&g_bstate[blk], AGG_READY | (unsigned)btot);  // publish agg
        int run = 0;
        for (int j = blk - 1; j >= 0; j--) {  // lookback
            unsigned st;
            do { st = atomicAdd(&g_bstate[j], 0u); } while (st < AGG_READY);
            run += (int)(st & 0x3FFFFFFFu);
            if (st & PFX_READY) break;
        }
        atomicExch(&g_bstate[blk], PFX_READY | (unsigned)(run + btot));
        sh_base = run;
    }
    __syncthreads();
    unsigned run = (unsigned)(sh_base + ex);
#pragma unroll
    for (int j = 0; j < 16; j++) { g_pref2[w0 + j] = run; run += __popc(wv[j]); }
}

// K3: thread per history voxel -------------------------------------------------
__global__ void k_maskH(const int4* __restrict__ hcoord,
                        const int* __restrict__ hbatch, int n) {
    int i = blockIdx.x * blockDim.x + threadIdx.x;
    if (i >= n) return;
    int4 c = hcoord[i];
    unsigned key = ((unsigned)c.x << 24) | ((unsigned)c.y << 16) |
                   ((unsigned)c.z << 8) | (unsigned)c.w;
    unsigned mask = mask27(g_bm1, key);
    unsigned pk = ((unsigned)hbatch[i] << 24) | (key & 0x00FFFFFFu);
    unsigned r2 = rank2_of(pk);
    bool cont = (g_cont[pk >> 5] >> (pk & 31)) & 1u;
    g_mr[i] = make_uint2(mask, r2 | (cont ? 0x80000000u : 0u));
    if (cont) {
        float* r = &g_pooled[(size_t)r2 * 32];
#pragma unroll
        for (int q = 0; q < 32; q++) r[q] = 0.0f;  // bits 0 = encoded minimum
    }
}

// K4 (profiled): warp per 8 history voxels (VPW=8) ------------------------------
__global__ void __launch_bounds__(256)
k_bb_pool(const float* __restrict__ hfeat,
          const float* __restrict__ Wbb,
          const int4* __restrict__ hcoord, int n) {
    int w0 = (int)((blockIdx.x * blockDim.x + threadIdx.x) >> 5) * 8;
    int lane = threadIdx.x & 31;
    if (w0 >= n) return;
    int cnt = n - w0;
    if (cnt > 8) cnt = 8;
    float wbb13 = Wbb[13 * 32 + lane];  // hoisted (L1-hot)
    uint2 mr[8];
    float hf[8];
#pragma unroll
    for (int j = 0; j < 8; j++)  // independent loads -> MLP 16
        if (j < cnt) mr[j] = g_mr[w0 + j];
#pragma unroll
    for (int j = 0; j < 8; j++)
        if (j < cnt) hf[j] = hfeat[w0 + j];
#pragma unroll
    for (int j = 0; j < 8; j++) {
        if (j >= cnt) break;
        int w = w0 + j;
        unsigned mask = mr[j].x;
        unsigned row = mr[j].y & 0x7FFFFFFFu;
        bool cont = (mr[j].y & 0x80000000u) != 0u;
        float acc;
        if (mask == (1u << 13)) {  // self-only: dominant fast path (~93%)
            acc = hf[j] * wbb13;
        } else {
            int4 c = hcoord[w];    // broadcast (L2-hot)
            unsigned key = ((unsigned)c.x << 24) | ((unsigned)c.y << 16) |
                           ((unsigned)c.z << 8) | (unsigned)c.w;
            int nhit = __popc(mask);
            float f = 0.0f;
            int d = 0;
            if (lane < nhit) {
                d = nth_bit(mask, lane);
                if (d == 13) {
                    f = hf[j];
                } else {
                    unsigned nk = key + c_delta[d];
                    unsigned s = hash1(nk);
                    while (g_h1_keys[s] != nk) s = (s + 1) & H1_MASK;
                    f = g_h1_feat[s];
                }
            }
            acc = 0.0f;
            for (int i = 0; i < nhit; i++) {  // ascending d == reference order
                float fd = __shfl_sync(FULL_MASK, f, i);
                int di = __shfl_sync(FULL_MASK, d, i);
                acc = fmaf(fd, Wbb[di * 32 + lane], acc);
            }
        }
        float* addr = &g_pooled[(size_t)row * 32 + lane];  // coalesced 128B
        if (cont) atomicMax((unsigned*)addr, encf(acc));
        else *addr = acc;
    }
}

// K5: thread per query point; write headers; zero no-hit rows; compact hits ----
__global__ void k_maskQ(const float* __restrict__ points,
                        const int4* __restrict__ qcoord,
                        float* __restrict__ out, int npts) {
    int p = blockIdx.x * blockDim.x + threadIdx.x;
    bool active = p < npts;
    unsigned mask = 0, key = 0;
    if (active) {
        int4 c = qcoord[p];  // b, x, y, z
        key = ((unsigned)c.x << 24) | ((unsigned)c.y << 16) |
              ((unsigned)c.z << 8) | (unsigned)c.w;
        mask = mask27(g_bm2, key);
        // header for every point (frees k_query from points/qcoord loads)
        const float* pt = points + (size_t)p * 5;
        float4* o = (float4*)(out + (size_t)p * 36);
        o[0] = make_float4(pt[0], pt[1], pt[2], pt[3]);
    }
    bool hit = active && (mask != 0u);
    unsigned bal = __ballot_sync(FULL_MASK, hit);
    if (hit) {  // warp-aggregated fat worklist append
        int lane = threadIdx.x & 31;
        int leader = __ffs(bal) - 1;
        int base = 0;
        if (lane == leader) base = atomicAdd(&g_wl_cnt, __popc(bal));
        base = __shfl_sync(bal, base, leader);
        g_wl[base + __popc(bal & ((1u << lane) - 1u))] =
            make_uint4((unsigned)p, mask, key, 0u);
    }
    if (active && !mask) {  // zero features for no-hit rows (~58%)
        float4* o = (float4*)(out + (size_t)p * 36);
        float4 z = make_float4(0.f, 0.f, 0.f, 0.f);
#pragma unroll
        for (int q = 1; q < 9; q++) o[q] = z;
    }
}

// K6: warp per 4 HIT query points (PPW=4) ---------------------------------------
__global__ void __launch_bounds__(256)
k_query(const float* __restrict__ Wc, float* __restrict__ out) {
    int gw = (int)((blockIdx.x * blockDim.x + threadIdx.x) >> 5);
    int lane = threadIdx.x & 31;
    int cnt = g_wl_cnt;
    int i0 = gw * 4;
    if (i0 >= cnt) return;
    int m = cnt - i0;
    if (m > 4) m = 4;
    uint4 e[4];
#pragma unroll
    for (int j = 0; j < 4; j++)  // independent sequential 16B loads
        if (j < m) e[j] = g_wl[i0 + j];
    // front-load per-lane metadata for all points (independent chains)
    int d[4], row[4];
    bool cont[4];
    int nhit[4];
#pragma unroll
    for (int j = 0; j < 4; j++) {
        d[j] = 0; row[j] = 0; cont[j] = false; nhit[j] = 0;
        if (j < m) {
            unsigned mask = e[j].y;
            nhit[j] = __popc(mask);
            if (lane < nhit[j]) {
                d[j] = nth_bit(mask, lane);
                unsigned rk = e[j].z + c_delta[d[j]];
                row[j] = (int)rank2_of(rk);
                cont[j] = (g_cont[rk >> 5] >> (rk & 31)) & 1u;
            }
        }
    }
#pragma unroll
    for (int j = 0; j < 4; j++) {
        if (j >= m) break;
        float acc = 0.0f;
        for (int i = 0; i < nhit[j]; i++) {  // ascending d == reference order
            int rowi = __shfl_sync(FULL_MASK, row[j], i);
            int di = __shfl_sync(FULL_MASK, d[j], i);
            int conti = __shfl_sync(FULL_MASK, (int)cont[j], i);
            const float4* prow = (const float4*)&g_pooled[(size_t)rowi * 32];
            const float* wb = Wc + di * 1024 + lane;
#pragma unroll
            for (int q = 0; q < 8; q++) {
                float4 v = prow[q];  // uniform address -> broadcast
                if (conti) {
                    v.x = decf(__float_as_uint(v.x));
                    v.y = decf(__float_as_uint(v.y));
                    v.z = decf(__float_as_uint(v.z));
                    v.w = decf(__float_as_uint(v.w));
                }
                acc = fmaf(v.x, wb[(q * 4 + 0) * 32], acc);
                acc = fmaf(v.y, wb[(q * 4 + 1) * 32], acc);
                acc = fmaf(v.z, wb[(q * 4 + 2) * 32], acc);
                acc = fmaf(v.w, wb[(q * 4 + 3) * 32], acc);
            }
        }
        out[(size_t)e[j].x * 36 + 4 + lane] = acc;
    }
}

// K7: tail cleanup — restore the all-zeros scratch invariant ---------------------
__global__ void k_cleanup(const int4* __restrict__ hcoord,
                          const int* __restrict__ hbatch, int n) {
    int i = blockIdx.x * blockDim.x + threadIdx.x;
    if (i == 0) g_wl_cnt = 0;
    if (i < NBLK2) g_bstate[i] = 0u;
    if (i >= n) return;
    int4 c = hcoord[i];
    unsigned key = ((unsigned)c.x << 24) | ((unsigned)c.y << 16) |
                   ((unsigned)c.z << 8) | (unsigned)c.w;
    unsigned pk = ((unsigned)hbatch[i] << 24) | (key & 0x00FFFFFFu);
    g_bm1[key >> 5] = 0u;
    g_bm2[pk >> 5] = 0u;
    g_cont[pk >> 5] = 0u;
    g_h1_keys[g_slotOf[i]] = 0u;
}

// ---------------------------------------------------------------------------
extern "C" void kernel_launch(void* const* d_in, const int* in_sizes, int n_in,
                              void* d_out, int out_size) {
    const float* hfeat  = (const float*)d_in[0];
    const float* points = (const float*)d_in[1];
    const float* Wbb    = (const float*)d_in[2];
    const float* Wc     = (const float*)d_in[3];
    const int4*  hcoord = (const int4*)d_in[4];
    const int*   hbatch = (const int*)d_in[5];
    const int4*  qcoord = (const int4*)d_in[6];
    float* out = (float*)d_out;

    int n    = in_sizes[5];      // history voxel count
    int npts = in_sizes[6] / 4;  // query point count

    const int TB = 256;
    int nb = (n + TB - 1) / TB;
    int qb = (npts + TB - 1) / TB;
    k_insert<<<nb, TB>>>(hfeat, hcoord, hbatch, n);
    k_scan<<<NBLK2, TB>>>();
    k_maskH<<<nb, TB>>>(hcoord, hbatch, n);
    {
        int blocks = (n + 63) / 64;  // 8 warps/block, 8 voxels/warp
        k_bb_pool<<<blocks, TB>>>(hfeat, Wbb, hcoord, n);
    }                                                 // 4th launch: profiled
    k_maskQ<<<qb, TB>>>(points, qcoord, out, npts);
    {
        // warp handles 4 worklist entries; worst case cnt = npts
        long long warps = ((long long)npts + 3) / 4;
        int blocks = (int)((warps + 7) / 8);          // 8 warps per block
        k_query<<<blocks, TB>>>(Wc, out);
    }
    k_cleanup<<<nb, TB>>>(hcoord, hbatch, n);
}

// round 17
// speedup vs baseline: 1.1016x; 1.1016x over previous
#include <cuda_runtime.h>
#include <cstdint>

// ---------------------------------------------------------------------------
// SparseResUQueryNet R17 = R15 (best: 227.4us; VPW=4, PPW=2) + demand-driven
// pooled rows:
//   k_maskQ runs BEFORE maskH/bb_pool and marks every pool cell any query
//   will read (g_qmark bitmap, ~220k atomicOr). maskH encodes the queried
//   bit into g_mr (bit30) and zeroes contested rows only when queried;
//   bb_pool skips non-queried voxels entirely (~71% of row computes/stores).
//   Query reads exactly the marked cells, so every row it touches is fresh.
//
// Keys: 28-bit ((t*256+x)*256+y)*256+z, t<16, coords in [1,250] (no byte
// carry under +-1). Pool keys 25-bit (b<2). Linear bitmaps bm1/bm2; pooled
// row = rank2(pk) = prefix-popcount over bm2 (single-pass decoupled-lookback
// scan). H1 hash key->feature (EMPTY=0; packed keys never 0 since z>=1),
// probed only for non-self neighbor hits (~45k). maskQ writes the 4-float
// output header for all points, zero-fills no-hit feature rows (~58%), and
// compacts hits into a fat worklist uint4{p, mask, key, 0}. Contested pool
// cells (~1%): detected at insert, pooled via order-preserving-uint
// atomicMax, decoded on read. Tail cleanup restores all-zeros scratch.
// Launches (7): insert, scan, maskQ, maskH(profiled), bb_pool, query, cleanup.
// ---------------------------------------------------------------------------

#define FULL_MASK 0xFFFFFFFFu
#define H1_LOG 21
#define H1_SIZE (1u << H1_LOG)
#define H1_MASK (H1_SIZE - 1u)
#define BM1_WORDS (1u << 23)
#define BM2_WORDS (1u << 20)
#define CHUNK2 4096
#define NBLK2 (BM2_WORDS / CHUNK2)   // 256
#define NMAX  (1u << 20)
#define AGG_READY 0x40000000u
#define PFX_READY 0x80000000u
#define MR_CONT 0x80000000u
#define MR_QUERIED 0x40000000u
#define MR_ROW 0x3FFFFFFFu

__device__ unsigned g_h1_keys[H1_SIZE];               // 8 MB (EMPTY = 0)
__device__ float    g_h1_feat[H1_SIZE];               // 8 MB
__device__ unsigned g_bm1[BM1_WORDS + 2];             // 32 MB (+pad)
__device__ unsigned g_bm2[BM2_WORDS + 2];             // 4 MB  (+pad)
__device__ unsigned g_cont[BM2_WORDS];                // 4 MB contested bits
__device__ unsigned g_qmark[BM2_WORDS];               // 4 MB queried-cell bits
__device__ unsigned g_pref2[BM2_WORDS];               // 4 MB word prefix
__device__ unsigned g_bstate[NBLK2];                  // lookback states
__device__ int      g_slotOf[NMAX];                   // 4 MB voxel -> H1 slot
__device__ uint2    g_mr[NMAX];                       // 8 MB (mask, row|flags)
__device__ float    g_pooled[(size_t)NMAX * 32];      // 128 MB
__device__ uint4    g_wl[NMAX * 2];                   // 32 MB {p, mask, key, 0}
__device__ int      g_wl_cnt;

// delta[d] = (dx<<16)+(dy<<8)+dz for d = (dx+1)*9+(dy+1)*3+(dz+1)
__constant__ unsigned c_delta[27] = {
    0xFFFEFEFFu, 0xFFFEFF00u, 0xFFFEFF01u,
    0xFFFEFFFFu, 0xFFFF0000u, 0xFFFF0001u,
    0xFFFF00FFu, 0xFFFF0100u, 0xFFFF0101u,
    0xFFFFFEFFu, 0xFFFFFF00u, 0xFFFFFF01u,
    0xFFFFFFFFu, 0x00000000u, 0x00000001u,
    0x000000FFu, 0x00000100u, 0x00000101u,
    0x0000FEFFu, 0x0000FF00u, 0x0000FF01u,
    0x0000FFFFu, 0x00010000u, 0x00010001u,
    0x000100FFu, 0x00010100u, 0x00010101u
};

__device__ __forceinline__ unsigned hash1(unsigned k) {
    return (k * 2654435761u) >> (32 - H1_LOG);
}
__device__ __forceinline__ unsigned encf(float f) {
    unsigned b = __float_as_uint(f);
    return b ^ (unsigned)(((int)b >> 31) | 0x80000000);
}
__device__ __forceinline__ float decf(unsigned u) {
    unsigned x = ((int)u < 0) ? (u ^ 0x80000000u) : ~u;
    return __uint_as_float(x);
}
// 3-bit window; 2nd word only when it spills past bit 31 (6.25%).
__device__ __forceinline__ unsigned tri_at(const unsigned* bm, unsigned bitpos) {
    unsigned idx = bitpos >> 5, sh = bitpos & 31;
    unsigned tri = (bm[idx] >> sh) & 7u;
    if (sh > 29u) tri |= (bm[idx + 1] << (32u - sh)) & 7u;
    return tri;
}
__device__ __forceinline__ unsigned mask27(const unsigned* bm, unsigned key) {
    unsigned mask = 0;
#pragma unroll
    for (int g = 0; g < 9; g++)
        mask |= tri_at(bm, key + c_delta[g * 3]) << (g * 3);
    return mask;
}
__device__ __forceinline__ unsigned rank2_of(unsigned pk) {
    unsigned w = pk >> 5, b = pk & 31;
    return g_pref2[w] + __popc(g_bm2[w] & ((1u << b) - 1u));
}
__device__ __forceinline__ int nth_bit(unsigned mask, int lane) {
    unsigned mm = mask;
    for (int t = 0; t < lane; t++) mm &= mm - 1;
    return __ffs(mm) - 1;
}
__device__ __forceinline__ int block_scan_excl(int v, int tid) {
    __shared__ int sh[256];
    sh[tid] = v;
    __syncthreads();
    for (int off = 1; off < 256; off <<= 1) {
        int add = (tid >= off) ? sh[tid - off] : 0;
        __syncthreads();
        sh[tid] += add;
        __syncthreads();
    }
    int incl = sh[tid];
    __syncthreads();
    return incl - v;
}

// K1: set bits, insert (key,feat) into H1 (record slot), detect contested ----
__global__ void k_insert(const float* __restrict__ hfeat,
                         const int4* __restrict__ hcoord,
                         const int* __restrict__ hbatch, int n) {
    int i = blockIdx.x * blockDim.x + threadIdx.x;
    if (i >= n) return;
    int4 c = hcoord[i];  // t, x, y, z
    unsigned key = ((unsigned)c.x << 24) | ((unsigned)c.y << 16) |
                   ((unsigned)c.z << 8) | (unsigned)c.w;  // never 0 (x,y,z>=1)
    atomicOr(&g_bm1[key >> 5], 1u << (key & 31));
    unsigned s = hash1(key);
    while (true) {  // history keys unique (np.unique upstream)
        unsigned old = atomicCAS(&g_h1_keys[s], 0u, key);
        if (old == 0u) { g_h1_feat[s] = hfeat[i]; g_slotOf[i] = (int)s; break; }
        s = (s + 1) & H1_MASK;
    }
    unsigned pk = ((unsigned)hbatch[i] << 24) | (key & 0x00FFFFFFu);
    unsigned bit = 1u << (pk & 31);
    unsigned prev = atomicOr(&g_bm2[pk >> 5], bit);
    if (prev & bit) atomicOr(&g_cont[pk >> 5], bit);
}

// K2: single-pass bm2 prefix scan (decoupled lookback) ------------------------
__global__ void k_scan() {
    int blk = blockIdx.x, tid = threadIdx.x;
    size_t w0 = (size_t)blk * CHUNK2 + (size_t)tid * 16;
    unsigned wv[16];
    int s = 0;
#pragma unroll
    for (int j = 0; j < 16; j++) { wv[j] = g_bm2[w0 + j]; s += __popc(wv[j]); }
    int ex = block_scan_excl(s, tid);
    __shared__ int sh_tot;
    __shared__ int sh_base;
    if (tid == 255) sh_tot = ex + s;
    __syncthreads();
    if (tid == 0) {
        int btot = sh_tot;
        atomicExch(&g_bstate[blk], AGG_READY | (unsigned)btot);  // publish agg
        int run = 0;
        for (int j = blk - 1; j >= 0; j--) {  // lookback
            unsigned st;
            do { st = atomicAdd(&g_bstate[j], 0u); } while (st < AGG_READY);
            run += (int)(st & 0x3FFFFFFFu);
            if (st & PFX_READY) break;
        }
        atomicExch(&g_bstate[blk], PFX_READY | (unsigned)(run + btot));
        sh_base = run;
    }
    __syncthreads();
    unsigned run = (unsigned)(sh_base + ex);
#pragma unroll
    for (int j = 0; j < 16; j++) { g_pref2[w0 + j] = run; run += __popc(wv[j]); }
}

// K3: thread per query point; mark queried cells; write headers; zero no-hit
// rows; compact hits into the fat worklist ------------------------------------
__global__ void k_maskQ(const float* __restrict__ points,
                        const int4* __restrict__ qcoord,
                        float* __restrict__ out, int npts) {
    int p = blockIdx.x * blockDim.x + threadIdx.x;
    bool active = p < npts;
    unsigned mask = 0, key = 0;
    if (active) {
        int4 c = qcoord[p];  // b, x, y, z
        key = ((unsigned)c.x << 24) | ((unsigned)c.y << 16) |
              ((unsigned)c.z << 8) | (unsigned)c.w;
        mask = mask27(g_bm2, key);
        // header for every point (frees k_query from points/qcoord loads)
        const float* pt = points + (size_t)p * 5;
        float4* o = (float4*)(out + (size_t)p * 36);
        o[0] = make_float4(pt[0], pt[1], pt[2], pt[3]);
        // mark every cell this point will read (avg ~1.3 per hit point)
        unsigned mm = mask;
        while (mm) {
            int d = __ffs(mm) - 1;
            mm &= mm - 1;
            unsigned rk = key + c_delta[d];
            atomicOr(&g_qmark[rk >> 5], 1u << (rk & 31));
        }
    }
    bool hit = active && (mask != 0u);
    unsigned bal = __ballot_sync(FULL_MASK, hit);
    if (hit) {  // warp-aggregated fat worklist append
        int lane = threadIdx.x & 31;
        int leader = __ffs(bal) - 1;
        int base = 0;
        if (lane == leader) base = atomicAdd(&g_wl_cnt, __popc(bal));
        base = __shfl_sync(bal, base, leader);
        g_wl[base + __popc(bal & ((1u << lane) - 1u))] =
            make_uint4((unsigned)p, mask, key, 0u);
    }
    if (active && !mask) {  // zero features for no-hit rows (~58%)
        float4* o = (float4*)(out + (size_t)p * 36);
        float4 z = make_float4(0.f, 0.f, 0.f, 0.f);
#pragma unroll
        for (int q = 1; q < 9; q++) o[q] = z;
    }
}

// K4 (profiled): thread per history voxel --------------------------------------
__global__ void k_maskH(const int4* __restrict__ hcoord,
                        const int* __restrict__ hbatch, int n) {
    int i = blockIdx.x * blockDim.x + threadIdx.x;
    if (i >= n) return;
    int4 c = hcoord[i];
    unsigned key = ((unsigned)c.x << 24) | ((unsigned)c.y << 16) |
                   ((unsigned)c.z << 8) | (unsigned)c.w;
    unsigned mask = mask27(g_bm1, key);
    unsigned pk = ((unsigned)hbatch[i] << 24) | (key & 0x00FFFFFFu);
    unsigned bit = pk & 31, w = pk >> 5;
    unsigned r2 = g_pref2[w] + __popc(g_bm2[w] & ((1u << bit) - 1u));
    bool cont = (g_cont[w] >> bit) & 1u;
    bool quer = (g_qmark[w] >> bit) & 1u;
    g_mr[i] = make_uint2(mask, r2 | (cont ? MR_CONT : 0u) |
                                   (quer ? MR_QUERIED : 0u));
    if (cont && quer) {
        float* r = &g_pooled[(size_t)r2 * 32];
#pragma unroll
        for (int q = 0; q < 32; q++) r[q] = 0.0f;  // bits 0 = encoded minimum
    }
}

// K5: warp per 4 history voxels (VPW=4); skip non-queried cells (~71%) ----------
__global__ void __launch_bounds__(256)
k_bb_pool(const float* __restrict__ hfeat,
          const float* __restrict__ Wbb,
          const int4* __restrict__ hcoord, int n) {
    int w0 = (int)((blockIdx.x * blockDim.x + threadIdx.x) >> 5) * 4;
    int lane = threadIdx.x & 31;
    if (w0 >= n) return;
    int cnt = n - w0;
    if (cnt > 4) cnt = 4;
    float wbb13 = Wbb[13 * 32 + lane];  // hoisted (L1-hot)
    uint2 mr[4];
    float hf[4];
#pragma unroll
    for (int j = 0; j < 4; j++)  // independent loads -> MLP 8
        if (j < cnt) mr[j] = g_mr[w0 + j];
#pragma unroll
    for (int j = 0; j < 4; j++)
        if (j < cnt) hf[j] = hfeat[w0 + j];
#pragma unroll
    for (int j = 0; j < 4; j++) {
        if (j >= cnt) break;
        if (!(mr[j].y & MR_QUERIED)) continue;  // row never read: skip
        int w = w0 + j;
        unsigned mask = mr[j].x;
        unsigned row = mr[j].y & MR_ROW;
        bool cont = (mr[j].y & MR_CONT) != 0u;
        float acc;
        if (mask == (1u << 13)) {  // self-only: dominant fast path (~93%)
            acc = hf[j] * wbb13;
        } else {
            int4 c = hcoord[w];    // broadcast (L2-hot)
            unsigned key = ((unsigned)c.x << 24) | ((unsigned)c.y << 16) |
                           ((unsigned)c.z << 8) | (unsigned)c.w;
            int nhit = __popc(mask);
            float f = 0.0f;
            int d = 0;
            if (lane < nhit) {
                d = nth_bit(mask, lane);
                if (d == 13) {
                    f = hf[j];
                } else {
                    unsigned nk = key + c_delta[d];
                    unsigned s = hash1(nk);
                    while (g_h1_keys[s] != nk) s = (s + 1) & H1_MASK;
                    f = g_h1_feat[s];
                }
            }
            acc = 0.0f;
            for (int i = 0; i < nhit; i++) {  // ascending d == reference order
                float fd = __shfl_sync(FULL_MASK, f, i);
                int di = __shfl_sync(FULL_MASK, d, i);
                acc = fmaf(fd, Wbb[di * 32 + lane], acc);
            }
        }
        float* addr = &g_pooled[(size_t)row * 32 + lane];  // coalesced 128B
        if (cont) atomicMax((unsigned*)addr, encf(acc));
        else *addr = acc;
    }
}

// K6: warp per 2 HIT query points (PPW=2) ---------------------------------------
__global__ void __launch_bounds__(256)
k_query(const float* __restrict__ Wc, float* __restrict__ out) {
    int gw = (int)((blockIdx.x * blockDim.x + threadIdx.x) >> 5);
    int lane = threadIdx.x & 31;
    int cnt = g_wl_cnt;
    int i0 = gw * 2;
    if (i0 >= cnt) return;
    int m = cnt - i0;
    if (m > 2) m = 2;
    uint4 e[2];
#pragma unroll
    for (int j = 0; j < 2; j++)  // independent sequential 16B loads
        if (j < m) e[j] = g_wl[i0 + j];
    int d[2], row[2];
    bool cont[2];
    int nhit[2];
#pragma unroll
    for (int j = 0; j < 2; j++) {
        d[j] = 0; row[j] = 0; cont[j] = false; nhit[j] = 0;
        if (j < m) {
            unsigned mask = e[j].y;
            nhit[j] = __popc(mask);
            if (lane < nhit[j]) {
                d[j] = nth_bit(mask, lane);
                unsigned rk = e[j].z + c_delta[d[j]];
                row[j] = (int)rank2_of(rk);
                cont[j] = (g_cont[rk >> 5] >> (rk & 31)) & 1u;
            }
        }
    }
#pragma unroll
    for (int j = 0; j < 2; j++) {
        if (j >= m) break;
        float acc = 0.0f;
        for (int i = 0; i < nhit[j]; i++) {  // ascending d == reference order
            int rowi = __shfl_sync(FULL_MASK, row[j], i);
            int di = __shfl_sync(FULL_MASK, d[j], i);
            int conti = __shfl_sync(FULL_MASK, (int)cont[j], i);
            const float4* prow = (const float4*)&g_pooled[(size_t)rowi * 32];
            const float* wb = Wc + di * 1024 + lane;
#pragma unroll
            for (int q = 0; q < 8; q++) {
                float4 v = prow[q];  // uniform address -> broadcast
                if (conti) {
                    v.x = decf(__float_as_uint(v.x));
                    v.y = decf(__float_as_uint(v.y));
                    v.z = decf(__float_as_uint(v.z));
                    v.w = decf(__float_as_uint(v.w));
                }
                acc = fmaf(v.x, wb[(q * 4 + 0) * 32], acc);
                acc = fmaf(v.y, wb[(q * 4 + 1) * 32], acc);
                acc = fmaf(v.z, wb[(q * 4 + 2) * 32], acc);
                acc = fmaf(v.w, wb[(q * 4 + 3) * 32], acc);
            }
        }
        out[(size_t)e[j].x * 36 + 4 + lane] = acc;
    }
}

// K7: tail cleanup — restore the all-zeros scratch invariant ---------------------
__global__ void k_cleanup(const int4* __restrict__ hcoord,
                          const int* __restrict__ hbatch, int n) {
    int i = blockIdx.x * blockDim.x + threadIdx.x;
    if (i == 0) g_wl_cnt = 0;
    if (i < NBLK2) g_bstate[i] = 0u;
    if (i >= n) return;
    int4 c = hcoord[i];
    unsigned key = ((unsigned)c.x << 24) | ((unsigned)c.y << 16) |
                   ((unsigned)c.z << 8) | (unsigned)c.w;
    unsigned pk = ((unsigned)hbatch[i] << 24) | (key & 0x00FFFFFFu);
    g_bm1[key >> 5] = 0u;
    g_bm2[pk >> 5] = 0u;
    g_cont[pk >> 5] = 0u;
    g_qmark[pk >> 5] = 0u;  // marked cells are occupied cells: all covered
    g_h1_keys[g_slotOf[i]] = 0u;
}

// ---------------------------------------------------------------------------
extern "C" void kernel_launch(void* const* d_in, const int* in_sizes, int n_in,
                              void* d_out, int out_size) {
    const float* hfeat  = (const float*)d_in[0];
    const float* points = (const float*)d_in[1];
    const float* Wbb    = (const float*)d_in[2];
    const float* Wc     = (const float*)d_in[3];
    const int4*  hcoord = (const int4*)d_in[4];
    const int*   hbatch = (const int*)d_in[5];
    const int4*  qcoord = (const int4*)d_in[6];
    float* out = (float*)d_out;

    int n    = in_sizes[5];      // history voxel count
    int npts = in_sizes[6] / 4;  // query point count

    const int TB = 256;
    int nb = (n + TB - 1) / TB;
    int qb = (npts + TB - 1) / TB;
    k_insert<<<nb, TB>>>(hfeat, hcoord, hbatch, n);
    k_scan<<<NBLK2, TB>>>();
    k_maskQ<<<qb, TB>>>(points, qcoord, out, npts);
    k_maskH<<<nb, TB>>>(hcoord, hbatch, n);           // 4th launch: profiled
    {
        int blocks = (n + 31) / 32;  // 8 warps/block, 4 voxels/warp
        k_bb_pool<<<blocks, TB>>>(hfeat, Wbb, hcoord, n);
    }
    {
        // warp handles 2 worklist entries; worst case cnt = npts
        long long warps = ((long long)npts + 1) / 2;
        int blocks = (int)((warps + 7) / 8);          // 8 warps per block
        k_query<<<blocks, TB>>>(Wc, out);
    }
    k_cleanup<<<nb, TB>>>(hcoord, hbatch, n);
}